// round 14
// baseline (speedup 1.0000x reference)
#include <cuda_runtime.h>

// True single-wave persistent grid: 148 SMs x 8 blocks/SM (regs forced <=32).
// R8 config — measured at the B300 LTS chip cap (~6300 B/cyc): this layout is
// bandwidth-optimal; only per-iteration issue overhead is trimmed here.
#define GRID 1184
#define TPB  256
#define NWARPS_TOTAL ((GRID * TPB) / 32)   // 9472
#define ROWS_PER_IT  2

// Per-block partials: {intersection, sum_actual, sum_desire}, plus a ticket
// counter for the last-block-done finalize. Counter is reset to 0 by the
// finalizing block itself, so graph replays stay deterministic.
__device__ float        g_pi[GRID];
__device__ float        g_pa[GRID];
__device__ float        g_pd[GRID];
__device__ unsigned int g_ticket;   // zero-initialized at module load

__global__ void __launch_bounds__(TPB, 8) dist_reduce_kernel(
    const float4* __restrict__ o1,
    const float4* __restrict__ o2,
    const float*  __restrict__ desire,
    int nrows,
    float* __restrict__ out)
{
    const int lane  = threadIdx.x & 31;
    const int wid   = threadIdx.x >> 5;
    const int gwarp = (blockIdx.x * TPB + threadIdx.x) >> 5;

    float inter = 0.0f, sa = 0.0f, sd = 0.0f;

    // 2 rows per iteration: 4 independent 16B streaming loads front-batched.
    // Dual-value warp reduce: after one cross-half fold of each accumulator,
    // lower half carries row0's partial, upper half row1's; one shared 4-step
    // butterfly finishes both (7 shuffles total instead of 10).
    for (int row = gwarp * ROWS_PER_IT; row < nrows;
         row += NWARPS_TOTAL * ROWS_PER_IT) {
        const size_t base = (size_t)row * 32;       // 32 float4 per row
        float4 a0 = __ldcs(&o1[base +      lane]);
        float4 b0 = __ldcs(&o2[base +      lane]);
        float4 a1 = __ldcs(&o1[base + 32 + lane]);
        float4 b1 = __ldcs(&o2[base + 32 + lane]);

        float dx, dy, dz, dw;
        dx = a0.x - b0.x; dy = a0.y - b0.y; dz = a0.z - b0.z; dw = a0.w - b0.w;
        float acc0 = dx*dx + dy*dy + dz*dz + dw*dw;
        dx = a1.x - b1.x; dy = a1.y - b1.y; dz = a1.z - b1.z; dw = a1.w - b1.w;
        float acc1 = dx*dx + dy*dy + dz*dz + dw*dw;

        acc0 += __shfl_xor_sync(0xffffffffu, acc0, 16);
        acc1 += __shfl_xor_sync(0xffffffffu, acc1, 16);
        float v = (lane < 16) ? acc0 : acc1;
        #pragma unroll
        for (int off = 8; off; off >>= 1)
            v += __shfl_xor_sync(0xffffffffu, v, off);
        // lanes 0-15 hold sum(row), lanes 16-31 hold sum(row+1)
        float v1 = __shfl_sync(0xffffffffu, v, 16);

        if (lane == 0) {
            float d0 = __ldg(&desire[row]);
            float d1 = __ldg(&desire[row + 1]);
            // dist > 0.625  <=>  dist^2 > 0.390625
            float act0 = (v  > 0.390625f) ? 1.0f : 0.0f;
            float act1 = (v1 > 0.390625f) ? 1.0f : 0.0f;
            inter += act0 * d0 + act1 * d1;
            sa    += act0 + act1;
            sd    += d0 + d1;
        }
    }

    // Block reduction over 8 warp leaders -> per-block partial.
    __shared__ float s[8][3];
    if (lane == 0) { s[wid][0] = inter; s[wid][1] = sa; s[wid][2] = sd; }
    __syncthreads();

    __shared__ unsigned int s_ticket;
    if (threadIdx.x == 0) {
        float i = 0.0f, a = 0.0f, d = 0.0f;
        #pragma unroll
        for (int w = 0; w < 8; w++) { i += s[w][0]; a += s[w][1]; d += s[w][2]; }
        g_pi[blockIdx.x] = i;
        g_pa[blockIdx.x] = a;
        g_pd[blockIdx.x] = d;
        __threadfence();
        s_ticket = atomicAdd(&g_ticket, 1u);
    }
    __syncthreads();

    // Last block to finish reduces all partials (L2-resident) and finalizes.
    if (s_ticket == GRID - 1) {
        const int tid = threadIdx.x;
        float i = 0.0f, a = 0.0f, d = 0.0f;
        #pragma unroll 4
        for (int k = tid; k < GRID; k += TPB) {
            i += g_pi[k];
            a += g_pa[k];
            d += g_pd[k];
        }
        #pragma unroll
        for (int off = 16; off; off >>= 1) {
            i += __shfl_xor_sync(0xffffffffu, i, off);
            a += __shfl_xor_sync(0xffffffffu, a, off);
            d += __shfl_xor_sync(0xffffffffu, d, off);
        }
        __shared__ float t[8][3];
        if (lane == 0) { t[wid][0] = i; t[wid][1] = a; t[wid][2] = d; }
        __syncthreads();
        if (tid == 0) {
            float ti = 0.0f, ta = 0.0f, td = 0.0f;
            #pragma unroll
            for (int w = 0; w < 8; w++) {
                ti += t[w][0]; ta += t[w][1]; td += t[w][2];
            }
            float uni = ta + td - ti;
            out[0] = (ti + 1e-6f) / (uni + 1e-6f);
            g_ticket = 0;   // reset for next graph replay
        }
    }
}

extern "C" void kernel_launch(void* const* d_in, const int* in_sizes, int n_in,
                              void* d_out, int out_size)
{
    const float4* o1     = (const float4*)d_in[0];
    const float4* o2     = (const float4*)d_in[1];
    const float*  desire = (const float*)d_in[2];
    float* out = (float*)d_out;

    const int nrows = in_sizes[2];  // desire has N elements (N x 1)

    dist_reduce_kernel<<<GRID, TPB>>>(o1, o2, desire, nrows, out);
}

// round 16
// speedup vs baseline: 1.1156x; 1.1156x over previous
#include <cuda_runtime.h>

// True single-wave persistent grid: 148 SMs x 8 blocks/SM (regs forced <=32).
// FINAL (R8 config): measured at the B300 LTS chip cap (~6300 B/cyc /
// 6295 GB/s). All tested deviations (4-row unroll, work stealing, two-wave,
// folded reduce) regressed; this layout is bandwidth-optimal for sm_103a.
#define GRID 1184
#define TPB  256
#define NWARPS_TOTAL ((GRID * TPB) / 32)   // 9472
#define ROWS_PER_IT  2

// Per-block partials: {intersection, sum_actual, sum_desire}, plus a ticket
// counter for the last-block-done finalize. Counter is reset to 0 by the
// finalizing block itself, so graph replays stay deterministic.
__device__ float        g_pi[GRID];
__device__ float        g_pa[GRID];
__device__ float        g_pd[GRID];
__device__ unsigned int g_ticket;   // zero-initialized at module load

__global__ void __launch_bounds__(TPB, 8) dist_reduce_kernel(
    const float4* __restrict__ o1,
    const float4* __restrict__ o2,
    const float*  __restrict__ desire,
    int nrows,
    float* __restrict__ out)
{
    const int lane  = threadIdx.x & 31;
    const int wid   = threadIdx.x >> 5;
    const int gwarp = (blockIdx.x * TPB + threadIdx.x) >> 5;

    float inter = 0.0f, sa = 0.0f, sd = 0.0f;

    // 2 rows per iteration: 4 independent 16B streaming loads front-batched
    // (2KB per warp per iter); 2 interleaved shuffle chains. Kept at 2 rows
    // so the kernel fits in 32 registers -> 8 resident blocks per SM.
    for (int row = gwarp * ROWS_PER_IT; row < nrows;
         row += NWARPS_TOTAL * ROWS_PER_IT) {
        const size_t base = (size_t)row * 32;       // 32 float4 per row
        float4 a0 = __ldcs(&o1[base +      lane]);
        float4 b0 = __ldcs(&o2[base +      lane]);
        float4 a1 = __ldcs(&o1[base + 32 + lane]);
        float4 b1 = __ldcs(&o2[base + 32 + lane]);

        float dx, dy, dz, dw;
        dx = a0.x - b0.x; dy = a0.y - b0.y; dz = a0.z - b0.z; dw = a0.w - b0.w;
        float acc0 = dx*dx + dy*dy + dz*dz + dw*dw;
        dx = a1.x - b1.x; dy = a1.y - b1.y; dz = a1.z - b1.z; dw = a1.w - b1.w;
        float acc1 = dx*dx + dy*dy + dz*dz + dw*dw;

        #pragma unroll
        for (int off = 16; off; off >>= 1) {
            acc0 += __shfl_xor_sync(0xffffffffu, acc0, off);
            acc1 += __shfl_xor_sync(0xffffffffu, acc1, off);
        }

        if (lane == 0) {
            float d0 = __ldg(&desire[row]);
            float d1 = __ldg(&desire[row + 1]);
            // dist > 0.625  <=>  dist^2 > 0.390625
            float act0 = (acc0 > 0.390625f) ? 1.0f : 0.0f;
            float act1 = (acc1 > 0.390625f) ? 1.0f : 0.0f;
            inter += act0 * d0 + act1 * d1;
            sa    += act0 + act1;
            sd    += d0 + d1;
        }
    }

    // Block reduction over 8 warp leaders -> per-block partial.
    __shared__ float s[8][3];
    if (lane == 0) { s[wid][0] = inter; s[wid][1] = sa; s[wid][2] = sd; }
    __syncthreads();

    __shared__ unsigned int s_ticket;
    if (threadIdx.x == 0) {
        float i = 0.0f, a = 0.0f, d = 0.0f;
        #pragma unroll
        for (int w = 0; w < 8; w++) { i += s[w][0]; a += s[w][1]; d += s[w][2]; }
        g_pi[blockIdx.x] = i;
        g_pa[blockIdx.x] = a;
        g_pd[blockIdx.x] = d;
        __threadfence();
        s_ticket = atomicAdd(&g_ticket, 1u);
    }
    __syncthreads();

    // Last block to finish reduces all partials (L2-resident) and finalizes.
    if (s_ticket == GRID - 1) {
        const int tid = threadIdx.x;
        float i = 0.0f, a = 0.0f, d = 0.0f;
        #pragma unroll 4
        for (int k = tid; k < GRID; k += TPB) {
            i += g_pi[k];
            a += g_pa[k];
            d += g_pd[k];
        }
        #pragma unroll
        for (int off = 16; off; off >>= 1) {
            i += __shfl_xor_sync(0xffffffffu, i, off);
            a += __shfl_xor_sync(0xffffffffu, a, off);
            d += __shfl_xor_sync(0xffffffffu, d, off);
        }
        __shared__ float t[8][3];
        if (lane == 0) { t[wid][0] = i; t[wid][1] = a; t[wid][2] = d; }
        __syncthreads();
        if (tid == 0) {
            float ti = 0.0f, ta = 0.0f, td = 0.0f;
            #pragma unroll
            for (int w = 0; w < 8; w++) {
                ti += t[w][0]; ta += t[w][1]; td += t[w][2];
            }
            float uni = ta + td - ti;
            out[0] = (ti + 1e-6f) / (uni + 1e-6f);
            g_ticket = 0;   // reset for next graph replay
        }
    }
}

extern "C" void kernel_launch(void* const* d_in, const int* in_sizes, int n_in,
                              void* d_out, int out_size)
{
    const float4* o1     = (const float4*)d_in[0];
    const float4* o2     = (const float4*)d_in[1];
    const float*  desire = (const float*)d_in[2];
    float* out = (float*)d_out;

    const int nrows = in_sizes[2];  // desire has N elements (N x 1)

    dist_reduce_kernel<<<GRID, TPB>>>(o1, o2, desire, nrows, out);
}